// round 15
// baseline (speedup 1.0000x reference)
#include <cuda_runtime.h>
#include <cuda_fp16.h>
#include <math.h>
#include <stdint.h>

// Fused LSTM cell, fp16 mma.sync m16n8k16 (f32 accum) + ldmatrix.
// R15: PERSISTENT kernel (296 CTAs = 2/SM, all resident) processing ~7
//      output tiles each with a continuous 3-stage ring, and the fp32->fp16
//      conversion folded in with a deadline schedule:
//        - global warps 0..2047 each own 6 rows of every k-chunk
//        - share of chunk c converted at step c-4 (chunks 0..3 in prologue)
//        - loads of chunk c gate on cnt[c]==2048 at step c-2 (first tile only)
//      All producers resident => gating cannot deadlock (induction on the
//      minimal stuck gate). Conversion traffic hides under the tensor-bound
//      mainloop's idle DRAM. No separate cvt kernel, no wave drains.

#define B_DIM 8192
#define H_DIM 1024
#define KTOT  2048
#define BM 128
#define NCTA 296
#define A_STAGE 16384
#define B_STAGE 16384
#define STAGE_BYTES (A_STAGE + B_STAGE)        // 32768
#define STAGES 3
#define SM_MBAR (STAGES * STAGE_BYTES)         // 98304: full[3], empty[3]
#define SM_CPREB (SM_MBAR + 48)                // c_prev-ready mbarrier
#define SM_CPRE (SM_MBAR + 128)                // c_prev tile 16KB
#define SMEM_TOTAL (SM_CPRE + 16384)           // 114816 (2 CTAs/SM)

__device__ __align__(128) __half A16[(size_t)B_DIM * KTOT];   // 32 MB
__device__ __align__(128) __half B16[(size_t)4096 * KTOT];    // 16 MB
__device__ int g_cnt[32 * 32];                 // per-chunk counters, 128B apart

__device__ __forceinline__ uint32_t smem_u32(const void* p) {
    uint32_t a;
    asm("{ .reg .u64 t; cvta.to.shared.u64 t, %1; cvt.u32.u64 %0, t; }" : "=r"(a) : "l"(p));
    return a;
}
__device__ __forceinline__ void cp16(uint32_t dst, const void* src) {
    asm volatile("cp.async.cg.shared.global [%0], [%1], 16;" :: "r"(dst), "l"(src));
}
__device__ __forceinline__ uint32_t h2u(__half2 h) {
    return *reinterpret_cast<uint32_t*>(&h);
}
__device__ __forceinline__ void mbar_init(uint32_t a, uint32_t cnt) {
    asm volatile("mbarrier.init.shared.b64 [%0], %1;" :: "r"(a), "r"(cnt) : "memory");
}
__device__ __forceinline__ void mbar_wait(uint32_t a, uint32_t par) {
    asm volatile(
        "{\n\t.reg .pred P;\n"
        "WL%=:\n\t"
        "mbarrier.try_wait.parity.acquire.cta.shared::cta.b64 P, [%0], %1, 0x989680;\n\t"
        "@P bra WD%=;\n\t"
        "bra WL%=;\n"
        "WD%=:\n\t}"
        :: "r"(a), "r"(par) : "memory");
}
__device__ __forceinline__ void mbar_arrive(uint32_t a) {
    asm volatile("mbarrier.arrive.release.cta.shared::cta.b64 _, [%0];" :: "r"(a) : "memory");
}
__device__ __forceinline__ void cpasync_arrive(uint32_t a) {
    asm volatile("cp.async.mbarrier.arrive.noinc.shared::cta.b64 [%0];" :: "r"(a) : "memory");
}
__device__ __forceinline__ void gate_chunk(int c) {
    const int* p = &g_cnt[c * 32];
    int v;
    do {
        asm volatile("ld.acquire.gpu.global.b32 %0, [%1];" : "=r"(v) : "l"(p) : "memory");
    } while (v < 2048);
}

// Warp gw (<2048) converts rows [gw*6, gw*6+6) of chunk c's 12288-row region
// (rows 0..8191 = A/x|h; 8192..12287 = B/Wx|Wh). Lane covers 2 halves.
__device__ __forceinline__ void convert_share(
    int c, int gw, int lane,
    const float* __restrict__ x, const float* __restrict__ hp,
    const float* __restrict__ Wx, const float* __restrict__ Wh)
{
    if (gw < 2048) {
        const int koff = (c & 15) * 64;
        const bool lo = (c < 16);
        const int r0 = gw * 6;
#pragma unroll
        for (int j = 0; j < 6; j++) {
            int r = r0 + j;
            const float* s;
            __half* d;
            if (r < 8192) {
                s = (lo ? x : hp) + (size_t)r * 1024 + koff;
                d = A16 + (size_t)r * 2048 + c * 64;
            } else {
                int rb = r - 8192;
                s = (lo ? Wx : Wh) + (size_t)rb * 1024 + koff;
                d = B16 + (size_t)rb * 2048 + c * 64;
            }
            float2 v = __ldcs((const float2*)s + lane);
            ((uint32_t*)d)[lane] = h2u(__floats2half2_rn(v.x, v.y));
        }
        __threadfence();
        __syncwarp();
        if (lane == 0) atomicAdd(&g_cnt[c * 32], 1);
    }
}

struct TileCtx {
    uint32_t sb;
    int tid, lane;
    int wm, wn;
    int a_row, a_kh, b_row, b_kh;
    float (*acc)[4][4];
};

template <int LBUF>
__device__ __forceinline__ void issue_loads_A(const TileCtx& t, int m0, int lk) {
    const int k0 = lk * 64;
    const uint32_t abase = t.sb + LBUF * STAGE_BYTES;
#pragma unroll
    for (int p = 0; p < 4; p++) {
        int ch = t.tid + p * 256;
        int row = ch >> 3, c = ch & 7;
        cp16(abase + row * 128 + ((c ^ (row & 7)) << 4),
             A16 + (size_t)(m0 + row) * KTOT + k0 + c * 8);
    }
}
template <int LBUF>
__device__ __forceinline__ void issue_loads_B(const TileCtx& t, int c0, int lk) {
    const int k0 = lk * 64;
    const uint32_t bbase = t.sb + LBUF * STAGE_BYTES + A_STAGE;
#pragma unroll
    for (int p = 0; p < 4; p++) {
        int ch = t.tid + p * 256;
        int row = ch >> 3, c = ch & 7;
        int wrow = ((row >> 3) & 3) * 1024 + c0 + (row >> 5) * 8 + (row & 7);
        cp16(bbase + row * 128 + ((c ^ (row & 7)) << 4),
             B16 + (size_t)wrow * KTOT + k0 + c * 8);
    }
}
__device__ __forceinline__ void issue_loads_cprev(
    const TileCtx& t, const float* __restrict__ c_prev, int m0, int c0) {
#pragma unroll
    for (int p = 0; p < 4; p++) {
        int ch = t.tid + p * 256;
        int row = ch >> 3, c = ch & 7;
        cp16(t.sb + SM_CPRE + row * 128 + ((c ^ (row & 7)) << 4),
             c_prev + (size_t)(m0 + row) * 1024 + c0 + c * 4);
    }
}

template <int BUF>
__device__ __forceinline__ void ldsm_ks(const TileCtx& t, int ks,
                                        uint32_t af[4][4], uint32_t bf[4][2]) {
    const uint32_t abuf = t.sb + BUF * STAGE_BYTES;
    const uint32_t bbuf = abuf + A_STAGE;
#pragma unroll
    for (int i = 0; i < 4; i++) {
        int ra = t.wm + i * 16 + t.a_row;
        int ck = ks * 2 + t.a_kh;
        uint32_t addr = abuf + ra * 128 + (((uint32_t)(ck ^ (ra & 7))) << 4);
        asm volatile(
            "ldmatrix.sync.aligned.m8n8.x4.shared.b16 {%0,%1,%2,%3}, [%4];"
            : "=r"(af[i][0]), "=r"(af[i][1]), "=r"(af[i][2]), "=r"(af[i][3])
            : "r"(addr));
    }
#pragma unroll
    for (int jp = 0; jp < 2; jp++) {
        int rn = t.wn + jp * 16 + t.b_row;
        int ck = ks * 2 + t.b_kh;
        uint32_t addr = bbuf + rn * 128 + (((uint32_t)(ck ^ (rn & 7))) << 4);
        asm volatile(
            "ldmatrix.sync.aligned.m8n8.x4.shared.b16 {%0,%1,%2,%3}, [%4];"
            : "=r"(bf[2 * jp][0]), "=r"(bf[2 * jp][1]),
              "=r"(bf[2 * jp + 1][0]), "=r"(bf[2 * jp + 1][1])
            : "r"(addr));
    }
}
__device__ __forceinline__ void mma_ks(const TileCtx& t,
                                       uint32_t af[4][4], uint32_t bf[4][2]) {
#pragma unroll
    for (int i = 0; i < 4; i++)
#pragma unroll
        for (int j = 0; j < 4; j++) {
            asm volatile(
                "mma.sync.aligned.m16n8k16.row.col.f32.f16.f16.f32 "
                "{%0,%1,%2,%3}, {%4,%5,%6,%7}, {%8,%9}, {%0,%1,%2,%3};"
                : "+f"(t.acc[i][j][0]), "+f"(t.acc[i][j][1]),
                  "+f"(t.acc[i][j][2]), "+f"(t.acc[i][j][3])
                : "r"(af[i][0]), "r"(af[i][1]), "r"(af[i][2]), "r"(af[i][3]),
                  "r"(bf[j][0]), "r"(bf[j][1]));
        }
}
template <int BUF>
__device__ __forceinline__ void compute_ks(const TileCtx& t, int ks) {
    uint32_t af[4][4], bf[4][2];
    ldsm_ks<BUF>(t, ks, af, bf);
    mma_ks(t, af, bf);
}

// One ring step (R8 ordering). gate_c >= 0: gate the load on chunk readiness.
template <int BUF>
__device__ __forceinline__ void tile_step(
    const TileCtx& t, bool load, bool skip_empty, int gate_c,
    int lm0, int lc0, int lk, uint32_t pf, uint32_t pe)
{
    constexpr int LBUF = (BUF + 2) % 3;
    mbar_wait(t.sb + SM_MBAR + BUF * 8, pf);
    compute_ks<BUF>(t, 0);
    if (load) {
        if (gate_c >= 0) gate_chunk(gate_c);
        if (!skip_empty) mbar_wait(t.sb + SM_MBAR + 24 + LBUF * 8, pe);
        issue_loads_A<LBUF>(t, lm0, lk);
    }
    compute_ks<BUF>(t, 1);
    if (load) {
        issue_loads_B<LBUF>(t, lc0, lk);
        cpasync_arrive(t.sb + SM_MBAR + LBUF * 8);
    }
    compute_ks<BUF>(t, 2);
    {
        uint32_t af[4][4], bf[4][2];
        ldsm_ks<BUF>(t, 3, af, bf);
        if (t.lane == 0) mbar_arrive(t.sb + SM_MBAR + 24 + BUF * 8);
        mma_ks(t, af, bf);
    }
}

__device__ __forceinline__ float fsigm(float v) {
    return 1.0f / (1.0f + __expf(-v));
}
__device__ __forceinline__ float ftanh(float v) {
    float e = __expf(2.0f * fabsf(v));
    float r = 1.0f - 2.0f / (e + 1.0f);
    return copysignf(r, v);
}

__device__ __forceinline__ void epilogue_tile(
    const TileCtx& t, char* smem, int warp, int ct, int m0, int c0,
    const float* __restrict__ bx, const float* __restrict__ bh,
    float* __restrict__ out)
{
    mbar_wait(t.sb + SM_CPREB, (uint32_t)(ct & 1));

    const size_t oh_off = (size_t)B_DIM * H_DIM;
    const int bcol = (warp & 3) * 8 + 2 * (t.lane & 3);
    const int hc_col = c0 + bcol;
    const int cp_chunk = 2 * (warp & 3) + ((t.lane & 3) >> 1);
    const int cp_byte  = 8 * ((t.lane & 3) & 1);

    const float b_i0 = __ldg(bx + 0 * 1024 + hc_col) + __ldg(bh + 0 * 1024 + hc_col);
    const float b_i1 = __ldg(bx + 0 * 1024 + hc_col + 1) + __ldg(bh + 0 * 1024 + hc_col + 1);
    const float b_f0 = __ldg(bx + 1 * 1024 + hc_col) + __ldg(bh + 1 * 1024 + hc_col);
    const float b_f1 = __ldg(bx + 1 * 1024 + hc_col + 1) + __ldg(bh + 1 * 1024 + hc_col + 1);
    const float b_o0 = __ldg(bx + 2 * 1024 + hc_col) + __ldg(bh + 2 * 1024 + hc_col);
    const float b_o1 = __ldg(bx + 2 * 1024 + hc_col + 1) + __ldg(bh + 2 * 1024 + hc_col + 1);
    const float b_g0 = __ldg(bx + 3 * 1024 + hc_col) + __ldg(bh + 3 * 1024 + hc_col);
    const float b_g1 = __ldg(bx + 3 * 1024 + hc_col + 1) + __ldg(bh + 3 * 1024 + hc_col + 1);

#pragma unroll
    for (int i = 0; i < 4; i++) {
        const int lrow0 = t.wm + i * 16 + (t.lane >> 2);
#pragma unroll
        for (int tt = 0; tt < 2; tt++) {
            const int lrow = lrow0 + tt * 8;
            const int row = m0 + lrow;
            const int k0 = tt * 2;
            float2 cp = *(const float2*)(smem + SM_CPRE + lrow * 128 +
                                         ((cp_chunk ^ (lrow & 7)) << 4) + cp_byte);

            float iv0 = t.acc[i][0][k0]     + b_i0;
            float iv1 = t.acc[i][0][k0 + 1] + b_i1;
            float fv0 = t.acc[i][1][k0]     + b_f0;
            float fv1 = t.acc[i][1][k0 + 1] + b_f1;
            float ov0 = t.acc[i][2][k0]     + b_o0;
            float ov1 = t.acc[i][2][k0 + 1] + b_o1;
            float gv0 = t.acc[i][3][k0]     + b_g0;
            float gv1 = t.acc[i][3][k0 + 1] + b_g1;

            float ig0 = fsigm(iv0), ig1 = fsigm(iv1);
            float fg0 = fsigm(fv0), fg1 = fsigm(fv1);
            float og0 = fsigm(ov0), og1 = fsigm(ov1);
            float gg0 = ftanh(gv0), gg1 = ftanh(gv1);

            float cv0 = fg0 * cp.x + ig0 * gg0;
            float cv1 = fg1 * cp.y + ig1 * gg1;
            float hv0 = og0 * ftanh(cv0);
            float hv1 = og1 * ftanh(cv1);

            __stcs((float2*)(out + (size_t)row * 1024 + hc_col),
                   make_float2(cv0, cv1));
            __stcs((float2*)(out + oh_off + (size_t)row * 1024 + hc_col),
                   make_float2(hv0, hv1));
        }
    }
    // reset accumulators for next tile
#pragma unroll
    for (int i = 0; i < 4; i++)
#pragma unroll
        for (int j = 0; j < 4; j++)
#pragma unroll
            for (int r = 0; r < 4; r++) t.acc[i][j][r] = 0.f;
}

__global__ void __launch_bounds__(256, 2) lstm_fused_kernel(
    const float* __restrict__ c_prev,
    const float* __restrict__ bx,
    const float* __restrict__ bh,
    float* __restrict__ out,
    const float* __restrict__ x,
    const float* __restrict__ hp,
    const float* __restrict__ Wx,
    const float* __restrict__ Wh)
{
    extern __shared__ char smem[];
    const uint32_t sb = smem_u32(smem);
    const int tid = threadIdx.x;
    const int warp = tid >> 5, lane = tid & 31;
    const int cta = blockIdx.x;
    const int gw = cta * 8 + warp;             // global warp id

    TileCtx t;
    t.sb = sb;
    t.tid = tid;
    t.lane = lane;
    t.wm = (warp >> 2) * 64;
    t.wn = (warp & 3) * 32;
    t.a_row = ((lane >> 3) & 1) * 8 + (lane & 7);
    t.a_kh  = lane >> 4;
    t.b_row = ((lane >> 4) & 1) * 8 + (lane & 7);
    t.b_kh  = (lane >> 3) & 1;

    if (tid == 0) {
#pragma unroll
        for (int s = 0; s < 3; s++) {
            mbar_init(sb + SM_MBAR + s * 8, 256);       // full[s]
            mbar_init(sb + SM_MBAR + 24 + s * 8, 8);    // empty[s]
        }
        mbar_init(sb + SM_CPREB, 256);                  // c_prev ready
    }

    float acc[4][4][4];
#pragma unroll
    for (int i = 0; i < 4; i++)
#pragma unroll
        for (int j = 0; j < 4; j++)
#pragma unroll
            for (int r = 0; r < 4; r++) acc[i][j][r] = 0.f;
    t.acc = acc;

    const int NT = (2048 - cta + NCTA - 1) / NCTA;     // 6 or 7 tiles
    const int NSTEPS = NT * 32;

    __syncthreads();   // mbarrier init visible

    // ---- prologue: convert shares of chunks 0..3, gated prefill, cprev ----
    convert_share(0, gw, lane, x, hp, Wx, Wh);
    convert_share(1, gw, lane, x, hp, Wx, Wh);
    convert_share(2, gw, lane, x, hp, Wx, Wh);
    convert_share(3, gw, lane, x, hp, Wx, Wh);

    int m0 = (cta >> 5) * 128;
    int c0 = (cta & 31) * 32;

    gate_chunk(0);
    issue_loads_A<0>(t, m0, 0);
    issue_loads_B<0>(t, c0, 0);
    cpasync_arrive(sb + SM_MBAR + 0 * 8);
    gate_chunk(1);
    issue_loads_A<1>(t, m0, 1);
    issue_loads_B<1>(t, c0, 1);
    cpasync_arrive(sb + SM_MBAR + 1 * 8);
    issue_loads_cprev(t, c_prev, m0, c0);
    cpasync_arrive(sb + SM_CPREB);

    int buf = 0;
    uint32_t pf = 0;
    int g = 0;

    // ---- first output tile: conversion duties + gating ----
    for (int kt = 0; kt < 32; ++kt, ++g) {
        if (kt < 28) convert_share(kt + 4, gw, lane, x, hp, Wx, Wh);
        const int lg = g + 2;
        const int lt = lg >> 5;
        const int Tl = cta + NCTA * lt;
        const int lm0 = (Tl >> 5) * 128, lc0 = (Tl & 31) * 32, lk = lg & 31;
        const int gate_c = (kt < 30) ? (kt + 2) : -1;
        const uint32_t pe = (buf == 0) ? (pf ^ 1) : pf;
        const bool skip = (g == 0);
        switch (buf) {
            case 0: tile_step<0>(t, true, skip, gate_c, lm0, lc0, lk, pf, pe); break;
            case 1: tile_step<1>(t, true, false, gate_c, lm0, lc0, lk, pf, pe); break;
            default: tile_step<2>(t, true, false, gate_c, lm0, lc0, lk, pf, pe); break;
        }
        if (++buf == 3) { buf = 0; pf ^= 1; }
    }
    epilogue_tile(t, smem, warp, 0, m0, c0, bx, bh, out);

    // ---- remaining tiles: clean ring ----
    for (int ct = 1; ct < NT; ++ct) {
        __syncthreads();   // all warps done reading prior cprev buffer
        const int Tc = cta + NCTA * ct;
        m0 = (Tc >> 5) * 128;
        c0 = (Tc & 31) * 32;
        issue_loads_cprev(t, c_prev, m0, c0);
        cpasync_arrive(sb + SM_CPREB);

        for (int kt = 0; kt < 32; ++kt, ++g) {
            const int lg = g + 2;
            const bool load = lg < NSTEPS;
            int lm0 = 0, lc0 = 0, lk = 0;
            if (load) {
                const int lt = lg >> 5;
                const int Tl = cta + NCTA * lt;
                lm0 = (Tl >> 5) * 128; lc0 = (Tl & 31) * 32; lk = lg & 31;
            }
            const uint32_t pe = (buf == 0) ? (pf ^ 1) : pf;
            switch (buf) {
                case 0: tile_step<0>(t, load, false, -1, lm0, lc0, lk, pf, pe); break;
                case 1: tile_step<1>(t, load, false, -1, lm0, lc0, lk, pf, pe); break;
                default: tile_step<2>(t, load, false, -1, lm0, lc0, lk, pf, pe); break;
            }
            if (++buf == 3) { buf = 0; pf ^= 1; }
        }
        epilogue_tile(t, smem, warp, ct, m0, c0, bx, bh, out);
    }
}

extern "C" void kernel_launch(void* const* d_in, const int* in_sizes, int n_in,
                              void* d_out, int out_size) {
    const float* x      = (const float*)d_in[0];
    const float* c_prev = (const float*)d_in[1];
    const float* h_prev = (const float*)d_in[2];
    const float* Wx     = (const float*)d_in[3];
    const float* bx     = (const float*)d_in[4];
    const float* Wh     = (const float*)d_in[5];
    const float* bh     = (const float*)d_in[6];
    float* out = (float*)d_out;

    void* cntp = nullptr;
    cudaGetSymbolAddress(&cntp, g_cnt);
    cudaMemsetAsync(cntp, 0, sizeof(int) * 32 * 32, 0);

    cudaFuncSetAttribute(lstm_fused_kernel,
                         cudaFuncAttributeMaxDynamicSharedMemorySize, SMEM_TOTAL);
    lstm_fused_kernel<<<NCTA, 256, SMEM_TOTAL>>>(c_prev, bx, bh, out,
                                                 x, h_prev, Wx, Wh);
}

// round 16
// speedup vs baseline: 1.3657x; 1.3657x over previous
#include <cuda_runtime.h>
#include <cuda_fp16.h>
#include <math.h>
#include <stdint.h>

// Fused LSTM cell, fp16 mma.sync m16n8k16 (f32 accum) + ldmatrix.
// R16 = R14 chassis (proven fastest: 128x128 CTA, 8 warps 64x32, 3-stage
//       mbarrier ring, 2 CTAs/SM, c_prev smem prefetch, __ldcs/__stcs) +
//       PDL overlap: GEMM launched with programmatic stream serialization,
//       runs its cvt-independent prologue (mbar init, bias, acc, c_prev
//       issue) before cudaGridDependencySynchronize(); cvt triggers early.
//       cvt widened to 16 halves/thread.
// Pass 0: convert x|h -> A16[8192x2048], Wx|Wh -> B16[4096x2048] (RN).

#define B_DIM 8192
#define H_DIM 1024
#define KTOT  2048
#define BM 128
#define BK 64
#define A_STAGE 16384
#define B_STAGE 16384
#define STAGE_BYTES (A_STAGE + B_STAGE)        // 32768
#define STAGES 3
#define NSTG (KTOT / BK)                       // 32
#define SM_BIAS (STAGES * STAGE_BYTES)         // 98304
#define SM_MBAR (SM_BIAS + 512)                // full[3] @ +0, empty[3] @ +24
#define SM_CPREB (SM_MBAR + 48)                // c_prev-ready mbarrier
#define SM_CPRE (SM_MBAR + 128)                // c_prev tile 16KB
#define SMEM_TOTAL (SM_CPRE + 16384)           // 115328 (2 CTAs/SM)

__device__ __align__(128) __half A16[(size_t)B_DIM * KTOT];   // 32 MB
__device__ __align__(128) __half B16[(size_t)4096 * KTOT];    // 16 MB

__device__ __forceinline__ uint32_t smem_u32(const void* p) {
    uint32_t a;
    asm("{ .reg .u64 t; cvta.to.shared.u64 t, %1; cvt.u32.u64 %0, t; }" : "=r"(a) : "l"(p));
    return a;
}
__device__ __forceinline__ void cp16(uint32_t dst, const void* src) {
    asm volatile("cp.async.cg.shared.global [%0], [%1], 16;" :: "r"(dst), "l"(src));
}
__device__ __forceinline__ uint32_t h2u(__half2 h) {
    return *reinterpret_cast<uint32_t*>(&h);
}
__device__ __forceinline__ void mbar_init(uint32_t a, uint32_t cnt) {
    asm volatile("mbarrier.init.shared.b64 [%0], %1;" :: "r"(a), "r"(cnt) : "memory");
}
__device__ __forceinline__ void mbar_wait(uint32_t a, uint32_t par) {
    asm volatile(
        "{\n\t.reg .pred P;\n"
        "WL%=:\n\t"
        "mbarrier.try_wait.parity.acquire.cta.shared::cta.b64 P, [%0], %1, 0x989680;\n\t"
        "@P bra WD%=;\n\t"
        "bra WL%=;\n"
        "WD%=:\n\t}"
        :: "r"(a), "r"(par) : "memory");
}
__device__ __forceinline__ void mbar_arrive(uint32_t a) {
    asm volatile("mbarrier.arrive.release.cta.shared::cta.b64 _, [%0];" :: "r"(a) : "memory");
}
__device__ __forceinline__ void cpasync_arrive(uint32_t a) {
    asm volatile("cp.async.mbarrier.arrive.noinc.shared::cta.b64 [%0];" :: "r"(a) : "memory");
}

// ---------------- Pass 0: fp32 -> fp16 conversion (K-concatenated) ----------
// 16 halves per thread (two uint4 stores). 6144 blocks x 256 threads.
__global__ void __launch_bounds__(256) cvt_kernel(
    const float* __restrict__ x, const float* __restrict__ hp,
    const float* __restrict__ Wx, const float* __restrict__ Wh)
{
    size_t t = (size_t)blockIdx.x * 256 + threadIdx.x;
    const size_t NA = (size_t)B_DIM * KTOT / 16;   // 1,048,576
    const float* src;
    __half* dst;
    if (t < NA) {
        size_t e = t * 16;
        int b = (int)(e >> 11), k = (int)(e & 2047);
        src = (k < 1024) ? x + (size_t)b * 1024 + k
                         : hp + (size_t)b * 1024 + (k - 1024);
        dst = A16 + e;
    } else {
        size_t e = (t - NA) * 16;
        int n = (int)(e >> 11), k = (int)(e & 2047);
        src = (k < 1024) ? Wx + (size_t)n * 1024 + k
                         : Wh + (size_t)n * 1024 + (k - 1024);
        dst = B16 + e;
    }
#pragma unroll
    for (int q = 0; q < 2; q++) {
        float4 v0 = __ldcs((const float4*)(src + q * 8));
        float4 v1 = __ldcs((const float4*)(src + q * 8 + 4));
        uint4 u;
        u.x = h2u(__floats2half2_rn(v0.x, v0.y));
        u.y = h2u(__floats2half2_rn(v0.z, v0.w));
        u.z = h2u(__floats2half2_rn(v1.x, v1.y));
        u.w = h2u(__floats2half2_rn(v1.z, v1.w));
        *(uint4*)(dst + q * 8) = u;
    }
    cudaTriggerProgrammaticLaunchCompletion();
}

// ---------------- Pass 1: GEMM + fused LSTM --------------------------------
struct TileCtx {
    uint32_t sb;
    int m0, c0, tid, lane;
    int wm, wn;
    int a_row, a_kh, b_row, b_kh;
    float (*acc)[4][4];
};

template <int LBUF>
__device__ __forceinline__ void issue_loads_A(const TileCtx& t, int kt) {
    const int k0 = kt * BK;
    const uint32_t abase = t.sb + LBUF * STAGE_BYTES;
#pragma unroll
    for (int p = 0; p < 4; p++) {
        int ch = t.tid + p * 256;
        int row = ch >> 3, c = ch & 7;
        cp16(abase + row * 128 + ((c ^ (row & 7)) << 4),
             A16 + (size_t)(t.m0 + row) * KTOT + k0 + c * 8);
    }
}
template <int LBUF>
__device__ __forceinline__ void issue_loads_B(const TileCtx& t, int kt) {
    const int k0 = kt * BK;
    const uint32_t bbase = t.sb + LBUF * STAGE_BYTES + A_STAGE;
#pragma unroll
    for (int p = 0; p < 4; p++) {
        int ch = t.tid + p * 256;
        int row = ch >> 3, c = ch & 7;
        int wrow = ((row >> 3) & 3) * 1024 + t.c0 + (row >> 5) * 8 + (row & 7);
        cp16(bbase + row * 128 + ((c ^ (row & 7)) << 4),
             B16 + (size_t)wrow * KTOT + k0 + c * 8);
    }
}
__device__ __forceinline__ void issue_loads_cprev(const TileCtx& t,
                                                  const float* __restrict__ c_prev) {
#pragma unroll
    for (int p = 0; p < 4; p++) {
        int ch = t.tid + p * 256;
        int row = ch >> 3, c = ch & 7;
        cp16(t.sb + SM_CPRE + row * 128 + ((c ^ (row & 7)) << 4),
             c_prev + (size_t)(t.m0 + row) * 1024 + t.c0 + c * 4);
    }
}

template <int BUF>
__device__ __forceinline__ void ldsm_ks(const TileCtx& t, int ks,
                                        uint32_t af[4][4], uint32_t bf[4][2]) {
    const uint32_t abuf = t.sb + BUF * STAGE_BYTES;
    const uint32_t bbuf = abuf + A_STAGE;
#pragma unroll
    for (int i = 0; i < 4; i++) {
        int ra = t.wm + i * 16 + t.a_row;
        int ck = ks * 2 + t.a_kh;
        uint32_t addr = abuf + ra * 128 + (((uint32_t)(ck ^ (ra & 7))) << 4);
        asm volatile(
            "ldmatrix.sync.aligned.m8n8.x4.shared.b16 {%0,%1,%2,%3}, [%4];"
            : "=r"(af[i][0]), "=r"(af[i][1]), "=r"(af[i][2]), "=r"(af[i][3])
            : "r"(addr));
    }
#pragma unroll
    for (int jp = 0; jp < 2; jp++) {
        int rn = t.wn + jp * 16 + t.b_row;
        int ck = ks * 2 + t.b_kh;
        uint32_t addr = bbuf + rn * 128 + (((uint32_t)(ck ^ (rn & 7))) << 4);
        asm volatile(
            "ldmatrix.sync.aligned.m8n8.x4.shared.b16 {%0,%1,%2,%3}, [%4];"
            : "=r"(bf[2 * jp][0]), "=r"(bf[2 * jp][1]),
              "=r"(bf[2 * jp + 1][0]), "=r"(bf[2 * jp + 1][1])
            : "r"(addr));
    }
}
__device__ __forceinline__ void mma_ks(const TileCtx& t,
                                       uint32_t af[4][4], uint32_t bf[4][2]) {
#pragma unroll
    for (int i = 0; i < 4; i++)
#pragma unroll
        for (int j = 0; j < 4; j++) {
            asm volatile(
                "mma.sync.aligned.m16n8k16.row.col.f32.f16.f16.f32 "
                "{%0,%1,%2,%3}, {%4,%5,%6,%7}, {%8,%9}, {%0,%1,%2,%3};"
                : "+f"(t.acc[i][j][0]), "+f"(t.acc[i][j][1]),
                  "+f"(t.acc[i][j][2]), "+f"(t.acc[i][j][3])
                : "r"(af[i][0]), "r"(af[i][1]), "r"(af[i][2]), "r"(af[i][3]),
                  "r"(bf[j][0]), "r"(bf[j][1]));
        }
}
template <int BUF>
__device__ __forceinline__ void compute_ks(const TileCtx& t, int ks) {
    uint32_t af[4][4], bf[4][2];
    ldsm_ks<BUF>(t, ks, af, bf);
    mma_ks(t, af, bf);
}

template <int BUF, bool LOAD, bool SKIP_EMPTY, bool ARRIVE>
__device__ __forceinline__ void tile_step(
    const TileCtx& t, int kt, uint32_t pf, uint32_t pe)
{
    constexpr int LBUF = (BUF + 2) % 3;
    mbar_wait(t.sb + SM_MBAR + BUF * 8, pf);
    compute_ks<BUF>(t, 0);
    if (LOAD) {
        if (!SKIP_EMPTY) mbar_wait(t.sb + SM_MBAR + 24 + LBUF * 8, pe);
        issue_loads_A<LBUF>(t, kt + 2);
    }
    compute_ks<BUF>(t, 1);
    if (LOAD) {
        issue_loads_B<LBUF>(t, kt + 2);
        cpasync_arrive(t.sb + SM_MBAR + LBUF * 8);
    }
    compute_ks<BUF>(t, 2);
    {
        uint32_t af[4][4], bf[4][2];
        ldsm_ks<BUF>(t, 3, af, bf);
        if (ARRIVE && t.lane == 0)
            mbar_arrive(t.sb + SM_MBAR + 24 + BUF * 8);
        mma_ks(t, af, bf);
    }
}

__device__ __forceinline__ float fsigm(float v) {
    return 1.0f / (1.0f + __expf(-v));
}
__device__ __forceinline__ float ftanh(float v) {
    float e = __expf(2.0f * fabsf(v));
    float r = 1.0f - 2.0f / (e + 1.0f);
    return copysignf(r, v);
}

__global__ void __launch_bounds__(256, 2) lstm_fused_kernel(
    const float* __restrict__ c_prev,
    const float* __restrict__ bx,
    const float* __restrict__ bh,
    float* __restrict__ out)
{
    extern __shared__ char smem[];
    const uint32_t sb = smem_u32(smem);
    const int tid = threadIdx.x;
    const int warp = tid >> 5, lane = tid & 31;

    TileCtx t;
    t.sb = sb;
    t.tid = tid;
    t.lane = lane;
    t.wm = (warp >> 2) * 64;
    t.wn = (warp & 3) * 32;
    t.m0 = blockIdx.y * BM;
    t.c0 = blockIdx.x * 32;
    t.a_row = ((lane >> 3) & 1) * 8 + (lane & 7);
    t.a_kh  = lane >> 4;
    t.b_row = ((lane >> 4) & 1) * 8 + (lane & 7);
    t.b_kh  = (lane >> 3) & 1;

    if (tid == 0) {
#pragma unroll
        for (int s = 0; s < 3; s++) {
            mbar_init(sb + SM_MBAR + s * 8, 256);       // full[s]
            mbar_init(sb + SM_MBAR + 24 + s * 8, 8);    // empty[s]
        }
        mbar_init(sb + SM_CPREB, 256);                  // c_prev ready
    }
    if (tid < 128) {
        int g = tid >> 5, col = tid & 31;
        ((float*)(smem + SM_BIAS))[tid] =
            bx[g * 1024 + t.c0 + col] + bh[g * 1024 + t.c0 + col];
    }

    float acc[4][4][4];
#pragma unroll
    for (int i = 0; i < 4; i++)
#pragma unroll
        for (int j = 0; j < 4; j++)
#pragma unroll
            for (int r = 0; r < 4; r++) acc[i][j][r] = 0.f;
    t.acc = acc;

    __syncthreads();   // mbarrier init + bias visible before any arrives

    // cvt-independent prefetch first (runs under PDL overlap window):
    issue_loads_cprev(t, c_prev);
    cpasync_arrive(sb + SM_CPREB);

    // wait for cvt grid completion (A16/B16 ready), then stage 0/1.
    cudaGridDependencySynchronize();

    issue_loads_A<0>(t, 0);
    issue_loads_B<0>(t, 0);
    cpasync_arrive(sb + SM_MBAR + 0 * 8);
    issue_loads_A<1>(t, 1);
    issue_loads_B<1>(t, 1);
    cpasync_arrive(sb + SM_MBAR + 1 * 8);

    uint32_t pf = 0;
    tile_step<0, true, true,  true>(t, 0, pf, 0);
    tile_step<1, true, false, true>(t, 1, pf, pf);
    tile_step<2, true, false, true>(t, 2, pf, pf);
    pf ^= 1;
    for (int m = 1; m < 10; m++) {
        tile_step<0, true, false, true>(t, 3 * m,     pf, pf ^ 1);
        tile_step<1, true, false, true>(t, 3 * m + 1, pf, pf);
        tile_step<2, true, false, true>(t, 3 * m + 2, pf, pf);
        pf ^= 1;
    }
    tile_step<0, false, false, false>(t, 30, pf, 0);
    tile_step<1, false, false, false>(t, 31, pf, 0);

    // ---- fused LSTM epilogue (c_prev from smem, streaming out stores) ----
    mbar_wait(sb + SM_CPREB, 0);

    const float* bs = (const float*)(smem + SM_BIAS);
    const size_t oh_off = (size_t)B_DIM * H_DIM;
    const int bcol = (warp & 3) * 8 + 2 * (lane & 3);
    const int hc_col = t.c0 + bcol;
    const int cp_chunk = 2 * (warp & 3) + ((lane & 3) >> 1);
    const int cp_byte  = 8 * ((lane & 3) & 1);

    const float b_i0 = bs[0 * 32 + bcol], b_i1 = bs[0 * 32 + bcol + 1];
    const float b_f0 = bs[1 * 32 + bcol], b_f1 = bs[1 * 32 + bcol + 1];
    const float b_o0 = bs[2 * 32 + bcol], b_o1 = bs[2 * 32 + bcol + 1];
    const float b_g0 = bs[3 * 32 + bcol], b_g1 = bs[3 * 32 + bcol + 1];

#pragma unroll
    for (int i = 0; i < 4; i++) {
        const int lrow0 = t.wm + i * 16 + (lane >> 2);
#pragma unroll
        for (int tt = 0; tt < 2; tt++) {
            const int lrow = lrow0 + tt * 8;
            const int row = t.m0 + lrow;
            const int k0 = tt * 2;
            float2 cp = *(const float2*)(smem + SM_CPRE + lrow * 128 +
                                         ((cp_chunk ^ (lrow & 7)) << 4) + cp_byte);

            float iv0 = acc[i][0][k0]     + b_i0;
            float iv1 = acc[i][0][k0 + 1] + b_i1;
            float fv0 = acc[i][1][k0]     + b_f0;
            float fv1 = acc[i][1][k0 + 1] + b_f1;
            float ov0 = acc[i][2][k0]     + b_o0;
            float ov1 = acc[i][2][k0 + 1] + b_o1;
            float gv0 = acc[i][3][k0]     + b_g0;
            float gv1 = acc[i][3][k0 + 1] + b_g1;

            float ig0 = fsigm(iv0), ig1 = fsigm(iv1);
            float fg0 = fsigm(fv0), fg1 = fsigm(fv1);
            float og0 = fsigm(ov0), og1 = fsigm(ov1);
            float gg0 = ftanh(gv0), gg1 = ftanh(gv1);

            float cv0 = fg0 * cp.x + ig0 * gg0;
            float cv1 = fg1 * cp.y + ig1 * gg1;
            float hv0 = og0 * ftanh(cv0);
            float hv1 = og1 * ftanh(cv1);

            __stcs((float2*)(out + (size_t)row * 1024 + hc_col),
                   make_float2(cv0, cv1));
            __stcs((float2*)(out + oh_off + (size_t)row * 1024 + hc_col),
                   make_float2(hv0, hv1));
        }
    }
}

extern "C" void kernel_launch(void* const* d_in, const int* in_sizes, int n_in,
                              void* d_out, int out_size) {
    const float* x      = (const float*)d_in[0];
    const float* c_prev = (const float*)d_in[1];
    const float* h_prev = (const float*)d_in[2];
    const float* Wx     = (const float*)d_in[3];
    const float* bx     = (const float*)d_in[4];
    const float* Wh     = (const float*)d_in[5];
    const float* bh     = (const float*)d_in[6];
    float* out = (float*)d_out;

    cvt_kernel<<<6144, 256>>>(x, h_prev, Wx, Wh);

    cudaFuncSetAttribute(lstm_fused_kernel,
                         cudaFuncAttributeMaxDynamicSharedMemorySize, SMEM_TOTAL);

    // PDL: GEMM may start early; its grid-dep-sync orders A16/B16 reads
    // after cvt's full completion.
    cudaLaunchConfig_t cfg = {};
    cfg.gridDim = dim3(H_DIM / 32, B_DIM / BM, 1);   // (32, 64)
    cfg.blockDim = dim3(256, 1, 1);
    cfg.dynamicSmemBytes = SMEM_TOTAL;
    cfg.stream = 0;
    cudaLaunchAttribute attr[1];
    attr[0].id = cudaLaunchAttributeProgrammaticStreamSerialization;
    attr[0].val.programmaticStreamSerializationAllowed = 1;
    cfg.attrs = attr;
    cfg.numAttrs = 1;
    cudaLaunchKernelEx(&cfg, lstm_fused_kernel, c_prev, bx, bh, out);
}

// round 17
// speedup vs baseline: 1.3848x; 1.0140x over previous
#include <cuda_runtime.h>
#include <cuda_fp16.h>
#include <math.h>
#include <stdint.h>

// Fused LSTM cell, fp16 mma.sync m16n8k16 (f32 accum) + ldmatrix.
// R17 = best-measured components combined:
//   - R14 cvt: 12288 blocks x 256 thr, 8 halves/thread (fastest measured)
//   - R16 PDL: GEMM launched with programmatic stream serialization; its
//     cvt-independent prologue (mbar init, bias, acc, c_prev cp.async)
//     runs before cudaGridDependencySynchronize()
//   - R14 GEMM chassis: 128x128 CTA, 8 warps 64x32, 3-stage mbarrier ring,
//     2 CTAs/SM, c_prev smem prefetch, __ldcs/__stcs cache hints.
// Pass 0: convert x|h -> A16[8192x2048], Wx|Wh -> B16[4096x2048] (RN).

#define B_DIM 8192
#define H_DIM 1024
#define KTOT  2048
#define BM 128
#define BK 64
#define A_STAGE 16384
#define B_STAGE 16384
#define STAGE_BYTES (A_STAGE + B_STAGE)        // 32768
#define STAGES 3
#define NSTG (KTOT / BK)                       // 32
#define SM_BIAS (STAGES * STAGE_BYTES)         // 98304
#define SM_MBAR (SM_BIAS + 512)                // full[3] @ +0, empty[3] @ +24
#define SM_CPREB (SM_MBAR + 48)                // c_prev-ready mbarrier
#define SM_CPRE (SM_MBAR + 128)                // c_prev tile 16KB
#define SMEM_TOTAL (SM_CPRE + 16384)           // 115328 (2 CTAs/SM)

__device__ __align__(128) __half A16[(size_t)B_DIM * KTOT];   // 32 MB
__device__ __align__(128) __half B16[(size_t)4096 * KTOT];    // 16 MB

__device__ __forceinline__ uint32_t smem_u32(const void* p) {
    uint32_t a;
    asm("{ .reg .u64 t; cvta.to.shared.u64 t, %1; cvt.u32.u64 %0, t; }" : "=r"(a) : "l"(p));
    return a;
}
__device__ __forceinline__ void cp16(uint32_t dst, const void* src) {
    asm volatile("cp.async.cg.shared.global [%0], [%1], 16;" :: "r"(dst), "l"(src));
}
__device__ __forceinline__ uint32_t h2u(__half2 h) {
    return *reinterpret_cast<uint32_t*>(&h);
}
__device__ __forceinline__ void mbar_init(uint32_t a, uint32_t cnt) {
    asm volatile("mbarrier.init.shared.b64 [%0], %1;" :: "r"(a), "r"(cnt) : "memory");
}
__device__ __forceinline__ void mbar_wait(uint32_t a, uint32_t par) {
    asm volatile(
        "{\n\t.reg .pred P;\n"
        "WL%=:\n\t"
        "mbarrier.try_wait.parity.acquire.cta.shared::cta.b64 P, [%0], %1, 0x989680;\n\t"
        "@P bra WD%=;\n\t"
        "bra WL%=;\n"
        "WD%=:\n\t}"
        :: "r"(a), "r"(par) : "memory");
}
__device__ __forceinline__ void mbar_arrive(uint32_t a) {
    asm volatile("mbarrier.arrive.release.cta.shared::cta.b64 _, [%0];" :: "r"(a) : "memory");
}
__device__ __forceinline__ void cpasync_arrive(uint32_t a) {
    asm volatile("cp.async.mbarrier.arrive.noinc.shared::cta.b64 [%0];" :: "r"(a) : "memory");
}

// ---------------- Pass 0: fp32 -> fp16 conversion (K-concatenated) ----------
// R14 geometry: 12288 blocks x 256 threads, 8 halves/thread.
__global__ void __launch_bounds__(256) cvt_kernel(
    const float* __restrict__ x, const float* __restrict__ hp,
    const float* __restrict__ Wx, const float* __restrict__ Wh)
{
    size_t t = (size_t)blockIdx.x * 256 + threadIdx.x;
    const size_t NA = (size_t)B_DIM * KTOT / 8;
    const float* src;
    __half* dst;
    if (t < NA) {
        size_t e = t * 8;
        int b = (int)(e >> 11), k = (int)(e & 2047);
        src = (k < 1024) ? x + (size_t)b * 1024 + k
                         : hp + (size_t)b * 1024 + (k - 1024);
        dst = A16 + e;
    } else {
        size_t e = (t - NA) * 8;
        int n = (int)(e >> 11), k = (int)(e & 2047);
        src = (k < 1024) ? Wx + (size_t)n * 1024 + k
                         : Wh + (size_t)n * 1024 + (k - 1024);
        dst = B16 + e;
    }
    float4 v0 = __ldcs((const float4*)src);
    float4 v1 = __ldcs((const float4*)(src + 4));
    uint4 u;
    u.x = h2u(__floats2half2_rn(v0.x, v0.y));
    u.y = h2u(__floats2half2_rn(v0.z, v0.w));
    u.z = h2u(__floats2half2_rn(v1.x, v1.y));
    u.w = h2u(__floats2half2_rn(v1.z, v1.w));
    *(uint4*)dst = u;
    cudaTriggerProgrammaticLaunchCompletion();
}

// ---------------- Pass 1: GEMM + fused LSTM --------------------------------
struct TileCtx {
    uint32_t sb;
    int m0, c0, tid, lane;
    int wm, wn;
    int a_row, a_kh, b_row, b_kh;
    float (*acc)[4][4];
};

template <int LBUF>
__device__ __forceinline__ void issue_loads_A(const TileCtx& t, int kt) {
    const int k0 = kt * BK;
    const uint32_t abase = t.sb + LBUF * STAGE_BYTES;
#pragma unroll
    for (int p = 0; p < 4; p++) {
        int ch = t.tid + p * 256;
        int row = ch >> 3, c = ch & 7;
        cp16(abase + row * 128 + ((c ^ (row & 7)) << 4),
             A16 + (size_t)(t.m0 + row) * KTOT + k0 + c * 8);
    }
}
template <int LBUF>
__device__ __forceinline__ void issue_loads_B(const TileCtx& t, int kt) {
    const int k0 = kt * BK;
    const uint32_t bbase = t.sb + LBUF * STAGE_BYTES + A_STAGE;
#pragma unroll
    for (int p = 0; p < 4; p++) {
        int ch = t.tid + p * 256;
        int row = ch >> 3, c = ch & 7;
        int wrow = ((row >> 3) & 3) * 1024 + t.c0 + (row >> 5) * 8 + (row & 7);
        cp16(bbase + row * 128 + ((c ^ (row & 7)) << 4),
             B16 + (size_t)wrow * KTOT + k0 + c * 8);
    }
}
__device__ __forceinline__ void issue_loads_cprev(const TileCtx& t,
                                                  const float* __restrict__ c_prev) {
#pragma unroll
    for (int p = 0; p < 4; p++) {
        int ch = t.tid + p * 256;
        int row = ch >> 3, c = ch & 7;
        cp16(t.sb + SM_CPRE + row * 128 + ((c ^ (row & 7)) << 4),
             c_prev + (size_t)(t.m0 + row) * 1024 + t.c0 + c * 4);
    }
}

template <int BUF>
__device__ __forceinline__ void ldsm_ks(const TileCtx& t, int ks,
                                        uint32_t af[4][4], uint32_t bf[4][2]) {
    const uint32_t abuf = t.sb + BUF * STAGE_BYTES;
    const uint32_t bbuf = abuf + A_STAGE;
#pragma unroll
    for (int i = 0; i < 4; i++) {
        int ra = t.wm + i * 16 + t.a_row;
        int ck = ks * 2 + t.a_kh;
        uint32_t addr = abuf + ra * 128 + (((uint32_t)(ck ^ (ra & 7))) << 4);
        asm volatile(
            "ldmatrix.sync.aligned.m8n8.x4.shared.b16 {%0,%1,%2,%3}, [%4];"
            : "=r"(af[i][0]), "=r"(af[i][1]), "=r"(af[i][2]), "=r"(af[i][3])
            : "r"(addr));
    }
#pragma unroll
    for (int jp = 0; jp < 2; jp++) {
        int rn = t.wn + jp * 16 + t.b_row;
        int ck = ks * 2 + t.b_kh;
        uint32_t addr = bbuf + rn * 128 + (((uint32_t)(ck ^ (rn & 7))) << 4);
        asm volatile(
            "ldmatrix.sync.aligned.m8n8.x4.shared.b16 {%0,%1,%2,%3}, [%4];"
            : "=r"(bf[2 * jp][0]), "=r"(bf[2 * jp][1]),
              "=r"(bf[2 * jp + 1][0]), "=r"(bf[2 * jp + 1][1])
            : "r"(addr));
    }
}
__device__ __forceinline__ void mma_ks(const TileCtx& t,
                                       uint32_t af[4][4], uint32_t bf[4][2]) {
#pragma unroll
    for (int i = 0; i < 4; i++)
#pragma unroll
        for (int j = 0; j < 4; j++) {
            asm volatile(
                "mma.sync.aligned.m16n8k16.row.col.f32.f16.f16.f32 "
                "{%0,%1,%2,%3}, {%4,%5,%6,%7}, {%8,%9}, {%0,%1,%2,%3};"
                : "+f"(t.acc[i][j][0]), "+f"(t.acc[i][j][1]),
                  "+f"(t.acc[i][j][2]), "+f"(t.acc[i][j][3])
                : "r"(af[i][0]), "r"(af[i][1]), "r"(af[i][2]), "r"(af[i][3]),
                  "r"(bf[j][0]), "r"(bf[j][1]));
        }
}
template <int BUF>
__device__ __forceinline__ void compute_ks(const TileCtx& t, int ks) {
    uint32_t af[4][4], bf[4][2];
    ldsm_ks<BUF>(t, ks, af, bf);
    mma_ks(t, af, bf);
}

template <int BUF, bool LOAD, bool SKIP_EMPTY, bool ARRIVE>
__device__ __forceinline__ void tile_step(
    const TileCtx& t, int kt, uint32_t pf, uint32_t pe)
{
    constexpr int LBUF = (BUF + 2) % 3;
    mbar_wait(t.sb + SM_MBAR + BUF * 8, pf);
    compute_ks<BUF>(t, 0);
    if (LOAD) {
        if (!SKIP_EMPTY) mbar_wait(t.sb + SM_MBAR + 24 + LBUF * 8, pe);
        issue_loads_A<LBUF>(t, kt + 2);
    }
    compute_ks<BUF>(t, 1);
    if (LOAD) {
        issue_loads_B<LBUF>(t, kt + 2);
        cpasync_arrive(t.sb + SM_MBAR + LBUF * 8);
    }
    compute_ks<BUF>(t, 2);
    {
        uint32_t af[4][4], bf[4][2];
        ldsm_ks<BUF>(t, 3, af, bf);
        if (ARRIVE && t.lane == 0)
            mbar_arrive(t.sb + SM_MBAR + 24 + BUF * 8);
        mma_ks(t, af, bf);
    }
}

__device__ __forceinline__ float fsigm(float v) {
    return 1.0f / (1.0f + __expf(-v));
}
__device__ __forceinline__ float ftanh(float v) {
    float e = __expf(2.0f * fabsf(v));
    float r = 1.0f - 2.0f / (e + 1.0f);
    return copysignf(r, v);
}

__global__ void __launch_bounds__(256, 2) lstm_fused_kernel(
    const float* __restrict__ c_prev,
    const float* __restrict__ bx,
    const float* __restrict__ bh,
    float* __restrict__ out)
{
    extern __shared__ char smem[];
    const uint32_t sb = smem_u32(smem);
    const int tid = threadIdx.x;
    const int warp = tid >> 5, lane = tid & 31;

    TileCtx t;
    t.sb = sb;
    t.tid = tid;
    t.lane = lane;
    t.wm = (warp >> 2) * 64;
    t.wn = (warp & 3) * 32;
    t.m0 = blockIdx.y * BM;
    t.c0 = blockIdx.x * 32;
    t.a_row = ((lane >> 3) & 1) * 8 + (lane & 7);
    t.a_kh  = lane >> 4;
    t.b_row = ((lane >> 4) & 1) * 8 + (lane & 7);
    t.b_kh  = (lane >> 3) & 1;

    if (tid == 0) {
#pragma unroll
        for (int s = 0; s < 3; s++) {
            mbar_init(sb + SM_MBAR + s * 8, 256);       // full[s]
            mbar_init(sb + SM_MBAR + 24 + s * 8, 8);    // empty[s]
        }
        mbar_init(sb + SM_CPREB, 256);                  // c_prev ready
    }
    if (tid < 128) {
        int g = tid >> 5, col = tid & 31;
        ((float*)(smem + SM_BIAS))[tid] =
            bx[g * 1024 + t.c0 + col] + bh[g * 1024 + t.c0 + col];
    }

    float acc[4][4][4];
#pragma unroll
    for (int i = 0; i < 4; i++)
#pragma unroll
        for (int j = 0; j < 4; j++)
#pragma unroll
            for (int r = 0; r < 4; r++) acc[i][j][r] = 0.f;
    t.acc = acc;

    __syncthreads();   // mbarrier init + bias visible before any arrives

    // cvt-independent prefetch first (runs under PDL overlap window):
    issue_loads_cprev(t, c_prev);
    cpasync_arrive(sb + SM_CPREB);

    // wait for cvt grid completion (A16/B16 ready), then stage 0/1.
    cudaGridDependencySynchronize();

    issue_loads_A<0>(t, 0);
    issue_loads_B<0>(t, 0);
    cpasync_arrive(sb + SM_MBAR + 0 * 8);
    issue_loads_A<1>(t, 1);
    issue_loads_B<1>(t, 1);
    cpasync_arrive(sb + SM_MBAR + 1 * 8);

    uint32_t pf = 0;
    tile_step<0, true, true,  true>(t, 0, pf, 0);
    tile_step<1, true, false, true>(t, 1, pf, pf);
    tile_step<2, true, false, true>(t, 2, pf, pf);
    pf ^= 1;
    for (int m = 1; m < 10; m++) {
        tile_step<0, true, false, true>(t, 3 * m,     pf, pf ^ 1);
        tile_step<1, true, false, true>(t, 3 * m + 1, pf, pf);
        tile_step<2, true, false, true>(t, 3 * m + 2, pf, pf);
        pf ^= 1;
    }
    tile_step<0, false, false, false>(t, 30, pf, 0);
    tile_step<1, false, false, false>(t, 31, pf, 0);

    // ---- fused LSTM epilogue (c_prev from smem, streaming out stores) ----
    mbar_wait(sb + SM_CPREB, 0);

    const float* bs = (const float*)(smem + SM_BIAS);
    const size_t oh_off = (size_t)B_DIM * H_DIM;
    const int bcol = (warp & 3) * 8 + 2 * (lane & 3);
    const int hc_col = t.c0 + bcol;
    const int cp_chunk = 2 * (warp & 3) + ((lane & 3) >> 1);
    const int cp_byte  = 8 * ((lane & 3) & 1);

    const float b_i0 = bs[0 * 32 + bcol], b_i1 = bs[0 * 32 + bcol + 1];
    const float b_f0 = bs[1 * 32 + bcol], b_f1 = bs[1 * 32 + bcol + 1];
    const float b_o0 = bs[2 * 32 + bcol], b_o1 = bs[2 * 32 + bcol + 1];
    const float b_g0 = bs[3 * 32 + bcol], b_g1 = bs[3 * 32 + bcol + 1];

#pragma unroll
    for (int i = 0; i < 4; i++) {
        const int lrow0 = t.wm + i * 16 + (lane >> 2);
#pragma unroll
        for (int tt = 0; tt < 2; tt++) {
            const int lrow = lrow0 + tt * 8;
            const int row = t.m0 + lrow;
            const int k0 = tt * 2;
            float2 cp = *(const float2*)(smem + SM_CPRE + lrow * 128 +
                                         ((cp_chunk ^ (lrow & 7)) << 4) + cp_byte);

            float iv0 = acc[i][0][k0]     + b_i0;
            float iv1 = acc[i][0][k0 + 1] + b_i1;
            float fv0 = acc[i][1][k0]     + b_f0;
            float fv1 = acc[i][1][k0 + 1] + b_f1;
            float ov0 = acc[i][2][k0]     + b_o0;
            float ov1 = acc[i][2][k0 + 1] + b_o1;
            float gv0 = acc[i][3][k0]     + b_g0;
            float gv1 = acc[i][3][k0 + 1] + b_g1;

            float ig0 = fsigm(iv0), ig1 = fsigm(iv1);
            float fg0 = fsigm(fv0), fg1 = fsigm(fv1);
            float og0 = fsigm(ov0), og1 = fsigm(ov1);
            float gg0 = ftanh(gv0), gg1 = ftanh(gv1);

            float cv0 = fg0 * cp.x + ig0 * gg0;
            float cv1 = fg1 * cp.y + ig1 * gg1;
            float hv0 = og0 * ftanh(cv0);
            float hv1 = og1 * ftanh(cv1);

            __stcs((float2*)(out + (size_t)row * 1024 + hc_col),
                   make_float2(cv0, cv1));
            __stcs((float2*)(out + oh_off + (size_t)row * 1024 + hc_col),
                   make_float2(hv0, hv1));
        }
    }
}

extern "C" void kernel_launch(void* const* d_in, const int* in_sizes, int n_in,
                              void* d_out, int out_size) {
    const float* x      = (const float*)d_in[0];
    const float* c_prev = (const float*)d_in[1];
    const float* h_prev = (const float*)d_in[2];
    const float* Wx     = (const float*)d_in[3];
    const float* bx     = (const float*)d_in[4];
    const float* Wh     = (const float*)d_in[5];
    const float* bh     = (const float*)d_in[6];
    float* out = (float*)d_out;

    cvt_kernel<<<12288, 256>>>(x, h_prev, Wx, Wh);

    cudaFuncSetAttribute(lstm_fused_kernel,
                         cudaFuncAttributeMaxDynamicSharedMemorySize, SMEM_TOTAL);

    // PDL: GEMM may start early; its grid-dep-sync orders A16/B16 reads
    // after cvt's full completion.
    cudaLaunchConfig_t cfg = {};
    cfg.gridDim = dim3(H_DIM / 32, B_DIM / BM, 1);   // (32, 64)
    cfg.blockDim = dim3(256, 1, 1);
    cfg.dynamicSmemBytes = SMEM_TOTAL;
    cfg.stream = 0;
    cudaLaunchAttribute attr[1];
    attr[0].id = cudaLaunchAttributeProgrammaticStreamSerialization;
    attr[0].val.programmaticStreamSerializationAllowed = 1;
    cfg.attrs = attr;
    cfg.numAttrs = 1;
    cudaLaunchKernelEx(&cfg, lstm_fused_kernel, c_prev, bx, bh, out);
}